// round 12
// baseline (speedup 1.0000x reference)
#include <cuda_runtime.h>
#include <cuda_fp16.h>
#include <cstdint>

// Problem constants: N=100000 nodes, D=128, E=1600000 edges.
#define MAX_N 100000
#define MAX_E 2000000
#define DD 128
#define BN_EPS 1e-5f

// Scratch (static __device__ — no allocations allowed)
__device__ __align__(16) __half g_xh[MAX_N * DD];    // fp16 mirror of x
__device__ __align__(16) __half g_aggh[MAX_N * DD];  // fp16 mean-aggregated feats
__device__ __align__(16) __half g_wlh[DD * DD];      // fp16 W_l
__device__ __align__(16) __half g_wrh[DD * DD];      // fp16 W_r
__device__ int   g_degi[MAX_N];
__device__ int   g_rowstart[MAX_N + 1];
__device__ int   g_cursor[MAX_N];
__device__ int   g_csr[MAX_E];
__device__ int   g_bsum[256];
__device__ int   g_boff[256];
__device__ __align__(16) float g_colsum[DD];
__device__ __align__(16) float g_colsumsq[DD];
__device__ __align__(16) float g_scale[DD];
__device__ __align__(16) float g_shift[DD];
__device__ int g_idx64;

// ---------------------------------------------------------------------------
// 1. zero degree hist + detect edge_index dtype (int64 => high words all 0)
__global__ void init_kernel(const int* __restrict__ ei32, int N) {
    int i = blockIdx.x * blockDim.x + threadIdx.x;
    if (i < N) g_degi[i] = 0;
    if (i == 0) {
        int ok = 1;
#pragma unroll
        for (int k = 0; k < 64; k++) ok &= (ei32[2 * k + 1] == 0);
        g_idx64 = ok;
    }
}

// 1b. fp16 mirrors: x (n8x groups of 8 floats), then W_l (2048), then W_r (2048)
__global__ void convert_kernel(const float* __restrict__ x,
                               const float* __restrict__ W_l,
                               const float* __restrict__ W_r,
                               int n8x) {
    int i = blockIdx.x * blockDim.x + threadIdx.x;
    const float* src;
    __half* dst;
    int idx;
    if (i < n8x) { src = x; dst = g_xh; idx = i; }
    else if (i < n8x + 2048) { src = W_l; dst = g_wlh; idx = i - n8x; }
    else if (i < n8x + 4096) { src = W_r; dst = g_wrh; idx = i - n8x - 2048; }
    else return;
    float4 a = reinterpret_cast<const float4*>(src)[2 * idx];
    float4 b = reinterpret_cast<const float4*>(src)[2 * idx + 1];
    __half2 h0 = __floats2half2_rn(a.x, a.y);
    __half2 h1 = __floats2half2_rn(a.z, a.w);
    __half2 h2 = __floats2half2_rn(b.x, b.y);
    __half2 h3 = __floats2half2_rn(b.z, b.w);
    uint4 o;
    o.x = *reinterpret_cast<uint32_t*>(&h0);
    o.y = *reinterpret_cast<uint32_t*>(&h1);
    o.z = *reinterpret_cast<uint32_t*>(&h2);
    o.w = *reinterpret_cast<uint32_t*>(&h3);
    reinterpret_cast<uint4*>(dst)[idx] = o;
}

// ---------------------------------------------------------------------------
// 2. degree histogram over dst — 4 edges per thread, vectorized loads
__global__ void hist_kernel(const void* __restrict__ ei_raw, int E) {
    int i4 = blockIdx.x * blockDim.x + threadIdx.x;
    int e = i4 * 4;
    if (e >= E) return;
    int d0, d1, d2, d3;
    bool full = (e + 4 <= E);
    if (g_idx64) {
        const long long* p = (const long long*)ei_raw + E;  // dst row
        if (full) {
            longlong2 a = reinterpret_cast<const longlong2*>(p + e)[0];
            longlong2 b = reinterpret_cast<const longlong2*>(p + e)[1];
            d0 = (int)a.x; d1 = (int)a.y; d2 = (int)b.x; d3 = (int)b.y;
        } else {
            d0 = (int)p[e];
            d1 = (e + 1 < E) ? (int)p[e + 1] : -1;
            d2 = (e + 2 < E) ? (int)p[e + 2] : -1;
            d3 = -1;
        }
    } else {
        const int* p = (const int*)ei_raw + E;
        if (full) {
            int4 a = reinterpret_cast<const int4*>(p + e)[0];
            d0 = a.x; d1 = a.y; d2 = a.z; d3 = a.w;
        } else {
            d0 = p[e];
            d1 = (e + 1 < E) ? p[e + 1] : -1;
            d2 = (e + 2 < E) ? p[e + 2] : -1;
            d3 = -1;
        }
    }
    atomicAdd(&g_degi[d0], 1);
    if (d1 >= 0 || full) atomicAdd(&g_degi[d1], 1);
    if (d2 >= 0 || full) atomicAdd(&g_degi[d2], 1);
    if (full) atomicAdd(&g_degi[d3], 1);
}

// 3. scan pass 1
__global__ void scan_p1_kernel(int N) {
    __shared__ int wsum[8];
    const int t = threadIdx.x;
    const int lane = t & 31, w = t >> 5;
    const int base = blockIdx.x * 1024 + t * 4;

    int v0 = 0, v1 = 0, v2 = 0, v3 = 0;
    if (base + 0 < N) v0 = g_degi[base + 0];
    if (base + 1 < N) v1 = g_degi[base + 1];
    if (base + 2 < N) v2 = g_degi[base + 2];
    if (base + 3 < N) v3 = g_degi[base + 3];
    const int s = v0 + v1 + v2 + v3;

    int incl = s;
#pragma unroll
    for (int o = 1; o < 32; o <<= 1) {
        int n = __shfl_up_sync(0xFFFFFFFFu, incl, o);
        if (lane >= o) incl += n;
    }
    if (lane == 31) wsum[w] = incl;
    __syncthreads();
    if (w == 0) {
        int ws = (lane < 8) ? wsum[lane] : 0;
#pragma unroll
        for (int o = 1; o < 8; o <<= 1) {
            int n = __shfl_up_sync(0xFFFFFFFFu, ws, o);
            if (lane >= o) ws += n;
        }
        if (lane < 8) wsum[lane] = ws;
    }
    __syncthreads();
    const int woff = (w > 0) ? wsum[w - 1] : 0;
    const int te = woff + incl - s;
    if (base + 0 < N) g_rowstart[base + 0] = te;
    if (base + 1 < N) g_rowstart[base + 1] = te + v0;
    if (base + 2 < N) g_rowstart[base + 2] = te + v0 + v1;
    if (base + 3 < N) g_rowstart[base + 3] = te + v0 + v1 + v2;
    if (t == 255) g_bsum[blockIdx.x] = woff + incl;
}

// 4. scan pass 2 (block totals) + zero BN stats
__global__ void scan_p2_kernel(int nb) {
    __shared__ int ws2[4];
    const int t = threadIdx.x;        // 128 threads
    const int lane = t & 31, w = t >> 5;
    int v = (t < nb) ? g_bsum[t] : 0;
    int incl = v;
#pragma unroll
    for (int o = 1; o < 32; o <<= 1) {
        int n = __shfl_up_sync(0xFFFFFFFFu, incl, o);
        if (lane >= o) incl += n;
    }
    if (lane == 31) ws2[w] = incl;
    __syncthreads();
    if (w == 0 && lane < 4) {
        int x = ws2[lane];
#pragma unroll
        for (int o = 1; o < 4; o <<= 1) {
            int n = __shfl_up_sync(0x0000000Fu, x, o);
            if (lane >= o) x += n;
        }
        ws2[lane] = x;
    }
    __syncthreads();
    incl += (w > 0) ? ws2[w - 1] : 0;
    g_boff[t] = incl - v;
    g_colsum[t] = 0.f;
    g_colsumsq[t] = 0.f;
}

// 5. scan pass 3
__global__ void scan_p3_kernel(int N, int E) {
    int i = blockIdx.x * blockDim.x + threadIdx.x;
    if (i < N) {
        int r = g_rowstart[i] + g_boff[i >> 10];
        g_rowstart[i] = r;
        g_cursor[i] = r;
    }
    if (i == 0) g_rowstart[N] = E;
}

// ---------------------------------------------------------------------------
// 6. CSR fill — 4 edges per thread, vectorized loads
__global__ void fill_kernel(const void* __restrict__ ei_raw, int E) {
    int i4 = blockIdx.x * blockDim.x + threadIdx.x;
    int e = i4 * 4;
    if (e >= E) return;
    int s0, s1, s2, s3, d0, d1, d2, d3;
    bool full = (e + 4 <= E);
    if (g_idx64) {
        const long long* ps = (const long long*)ei_raw;
        const long long* pd = ps + E;
        if (full) {
            longlong2 a = reinterpret_cast<const longlong2*>(ps + e)[0];
            longlong2 b = reinterpret_cast<const longlong2*>(ps + e)[1];
            longlong2 c = reinterpret_cast<const longlong2*>(pd + e)[0];
            longlong2 f = reinterpret_cast<const longlong2*>(pd + e)[1];
            s0 = (int)a.x; s1 = (int)a.y; s2 = (int)b.x; s3 = (int)b.y;
            d0 = (int)c.x; d1 = (int)c.y; d2 = (int)f.x; d3 = (int)f.y;
        } else {
            s0 = (int)ps[e]; d0 = (int)pd[e];
            s1 = (e + 1 < E) ? (int)ps[e + 1] : 0; d1 = (e + 1 < E) ? (int)pd[e + 1] : -1;
            s2 = (e + 2 < E) ? (int)ps[e + 2] : 0; d2 = (e + 2 < E) ? (int)pd[e + 2] : -1;
            s3 = 0; d3 = -1;
        }
    } else {
        const int* ps = (const int*)ei_raw;
        const int* pd = ps + E;
        if (full) {
            int4 a = reinterpret_cast<const int4*>(ps + e)[0];
            int4 c = reinterpret_cast<const int4*>(pd + e)[0];
            s0 = a.x; s1 = a.y; s2 = a.z; s3 = a.w;
            d0 = c.x; d1 = c.y; d2 = c.z; d3 = c.w;
        } else {
            s0 = ps[e]; d0 = pd[e];
            s1 = (e + 1 < E) ? ps[e + 1] : 0; d1 = (e + 1 < E) ? pd[e + 1] : -1;
            s2 = (e + 2 < E) ? ps[e + 2] : 0; d2 = (e + 2 < E) ? pd[e + 2] : -1;
            s3 = 0; d3 = -1;
        }
    }
    { int pos = atomicAdd(&g_cursor[d0], 1); g_csr[pos] = s0; }
    if (full || d1 >= 0) { int pos = atomicAdd(&g_cursor[d1], 1); g_csr[pos] = s1; }
    if (full || d2 >= 0) { int pos = atomicAdd(&g_cursor[d2], 1); g_csr[pos] = s2; }
    if (full)            { int pos = atomicAdd(&g_cursor[d3], 1); g_csr[pos] = s3; }
}

// ---------------------------------------------------------------------------
// 7. Gather-aggregate over fp16 mirror; one HALF-WARP per node. [R9 version]
__device__ __forceinline__ void accum8(float* acc, uint4 v) {
    float2 f;
    f = __half22float2(*reinterpret_cast<__half2*>(&v.x)); acc[0] += f.x; acc[1] += f.y;
    f = __half22float2(*reinterpret_cast<__half2*>(&v.y)); acc[2] += f.x; acc[3] += f.y;
    f = __half22float2(*reinterpret_cast<__half2*>(&v.z)); acc[4] += f.x; acc[5] += f.y;
    f = __half22float2(*reinterpret_cast<__half2*>(&v.w)); acc[6] += f.x; acc[7] += f.y;
}

__global__ __launch_bounds__(256)
void gather_kernel(int N) {
    const int warp = (blockIdx.x * blockDim.x + threadIdx.x) >> 5;
    const int lane = threadIdx.x & 31;
    const int half_id = lane >> 4;
    const int sub = lane & 15;
    const int node = warp * 2 + half_id;
    const unsigned hmask = half_id ? 0xFFFF0000u : 0x0000FFFFu;
    const int hbase = half_id << 4;

    int start = 0, end = 0;
    if (node < N) {
        start = g_rowstart[node];
        end   = g_rowstart[node + 1];
    }

    float acc[8];
#pragma unroll
    for (int k = 0; k < 8; k++) acc[k] = 0.f;

    const uint4* xh = reinterpret_cast<const uint4*>(g_xh);  // 16 uint4 per row

    for (int eb = start; eb < end; eb += 16) {
        int n = end - eb; if (n > 16) n = 16;
        int myid = (sub < n) ? g_csr[eb + sub] : 0;
        int j = 0;
        for (; j + 2 <= n; j += 2) {
            int s0 = __shfl_sync(hmask, myid, hbase + j);
            int s1 = __shfl_sync(hmask, myid, hbase + j + 1);
            uint4 v0 = xh[(size_t)s0 * 16 + sub];
            uint4 v1 = xh[(size_t)s1 * 16 + sub];
            accum8(acc, v0);
            accum8(acc, v1);
        }
        if (j < n) {
            int s0 = __shfl_sync(hmask, myid, hbase + j);
            uint4 v0 = xh[(size_t)s0 * 16 + sub];
            accum8(acc, v0);
        }
    }

    if (node < N) {
        const float inv = 1.0f / fmaxf((float)(end - start), 1.0f);
        __half2 h0 = __floats2half2_rn(acc[0] * inv, acc[1] * inv);
        __half2 h1 = __floats2half2_rn(acc[2] * inv, acc[3] * inv);
        __half2 h2 = __floats2half2_rn(acc[4] * inv, acc[5] * inv);
        __half2 h3 = __floats2half2_rn(acc[6] * inv, acc[7] * inv);
        uint4 o;
        o.x = *reinterpret_cast<uint32_t*>(&h0);
        o.y = *reinterpret_cast<uint32_t*>(&h1);
        o.z = *reinterpret_cast<uint32_t*>(&h2);
        o.w = *reinterpret_cast<uint32_t*>(&h3);
        reinterpret_cast<uint4*>(g_aggh + (size_t)node * DD)[sub] = o;
    }
}

// ---------------------------------------------------------------------------
// cp.async helper: 16B copy with zero-fill when pred is false (src-size=0)
__device__ __forceinline__ void cp16(uint32_t dst_smem, const void* src, bool pred) {
    int sz = pred ? 16 : 0;
    asm volatile("cp.async.cg.shared.global [%0], [%1], 16, %2;"
                 :: "r"(dst_smem), "l"(src), "r"(sz));
}

// ---------------------------------------------------------------------------
// 8. HMMA GEMM with cp.async 2-stage pipeline. [R11 version]
__global__ __launch_bounds__(256, 2)
void gemm_hmma_kernel(const float* __restrict__ b_l,
                      float* __restrict__ out,
                      int N) {
    __shared__ __align__(16) __half sA[2][128 * 40];
    __shared__ __align__(16) __half sB[2][128 * 40];

    const int tid = threadIdx.x;
    const int lane = tid & 31;
    const int wid = tid >> 5;
    const int warp_m = wid & 3;
    const int warp_n = wid >> 2;
    const int rowBase = blockIdx.x * 128;

    float d[2][8][4];
#pragma unroll
    for (int mt = 0; mt < 2; mt++)
#pragma unroll
        for (int nt = 0; nt < 8; nt++)
#pragma unroll
            for (int r = 0; r < 4; r++) d[mt][nt][r] = 0.f;

    const int lr = tid >> 1;          // 0..127: row in tile
    const int lc = (tid & 1) * 16;    // 0 or 16: half-offset within 32
    const int row = rowBase + lr;
    const bool rvalid = row < N;
    const int rclamp = rvalid ? row : 0;

    auto issue_tile = [&](int kt, int st) {
        const __half* srcA = (kt < 4) ? g_aggh : g_xh;
        const __half* srcB = (kt < 4) ? g_wlh : g_wrh;
        const __half* pa = srcA + (size_t)rclamp * DD + (kt & 3) * 32 + lc;
        const __half* pb = srcB + (size_t)lr * DD + (kt & 3) * 32 + lc;
        uint32_t da = (uint32_t)__cvta_generic_to_shared(&sA[st][lr * 40 + lc]);
        uint32_t db = (uint32_t)__cvta_generic_to_shared(&sB[st][lr * 40 + lc]);
        cp16(da, pa, rvalid);
        cp16(da + 16, pa + 8, rvalid);
        cp16(db, pb, true);
        cp16(db + 16, pb + 8, true);
        asm volatile("cp.async.commit_group;");
    };

    issue_tile(0, 0);

    for (int kt = 0; kt < 8; kt++) {
        const int cur = kt & 1;
        if (kt < 7) {
            issue_tile(kt + 1, cur ^ 1);
            asm volatile("cp.async.wait_group 1;");
        } else {
            asm volatile("cp.async.wait_group 0;");
        }
        __syncthreads();

#pragma unroll
        for (int ks = 0; ks < 32; ks += 16) {
            uint32_t a[2][4];
#pragma unroll
            for (int mt = 0; mt < 2; mt++) {
                int arow = warp_m * 32 + mt * 16 + (lane & 15);
                int akk = ks + ((lane >> 4) << 3);
                uint32_t addr = (uint32_t)__cvta_generic_to_shared(&sA[cur][arow * 40 + akk]);
                asm volatile(
                    "ldmatrix.sync.aligned.m8n8.x4.shared.b16 {%0,%1,%2,%3}, [%4];"
                    : "=r"(a[mt][0]), "=r"(a[mt][1]), "=r"(a[mt][2]), "=r"(a[mt][3])
                    : "r"(addr));
            }
            uint32_t b[8][2];
#pragma unroll
            for (int nt = 0; nt < 8; nt++) {
                int brow = warp_n * 64 + nt * 8 + (lane & 7);
                int bkk = ks + ((lane & 8) ? 8 : 0);
                uint32_t addr = (uint32_t)__cvta_generic_to_shared(&sB[cur][brow * 40 + bkk]);
                asm volatile(
                    "ldmatrix.sync.aligned.m8n8.x2.shared.b16 {%0,%1}, [%2];"
                    : "=r"(b[nt][0]), "=r"(b[nt][1])
                    : "r"(addr));
            }
#pragma unroll
            for (int mt = 0; mt < 2; mt++)
#pragma unroll
                for (int nt = 0; nt < 8; nt++) {
                    asm volatile(
                        "mma.sync.aligned.m16n8k16.row.col.f32.f16.f16.f32 "
                        "{%0,%1,%2,%3}, {%4,%5,%6,%7}, {%8,%9}, {%0,%1,%2,%3};"
                        : "+f"(d[mt][nt][0]), "+f"(d[mt][nt][1]),
                          "+f"(d[mt][nt][2]), "+f"(d[mt][nt][3])
                        : "r"(a[mt][0]), "r"(a[mt][1]), "r"(a[mt][2]), "r"(a[mt][3]),
                          "r"(b[nt][0]), "r"(b[nt][1]));
                }
        }
        __syncthreads();
    }

    // --- epilogue: +bias, relu, store fp32 h ---
#pragma unroll
    for (int nt = 0; nt < 8; nt++) {
        int col = warp_n * 64 + nt * 8 + ((lane & 3) << 1);
        float b0 = __ldg(&b_l[col]);
        float b1 = __ldg(&b_l[col + 1]);
#pragma unroll
        for (int mt = 0; mt < 2; mt++) {
            int orow = rowBase + warp_m * 32 + mt * 16 + (lane >> 2);
            if (orow < N) {
                float2 v = make_float2(fmaxf(d[mt][nt][0] + b0, 0.f),
                                       fmaxf(d[mt][nt][1] + b1, 0.f));
                *reinterpret_cast<float2*>(out + (size_t)orow * DD + col) = v;
            }
            if (orow + 8 < N) {
                float2 v = make_float2(fmaxf(d[mt][nt][2] + b0, 0.f),
                                       fmaxf(d[mt][nt][3] + b1, 0.f));
                *reinterpret_cast<float2*>(out + (size_t)(orow + 8) * DD + col) = v;
            }
        }
    }
}

// ---------------------------------------------------------------------------
// 9. BN column stats over out (h). One block per 128 rows. [R9 version]
__global__ __launch_bounds__(256)
void bn_stats_kernel(const float* __restrict__ out, int N) {
    __shared__ float ss[256], qq[256];
    const int tid = threadIdx.x;
    const int col = tid & 127;
    const int h = tid >> 7;
    const int rowBase = blockIdx.x * 128;

    float s = 0.f, q = 0.f;
    for (int r = h; r < 128; r += 2) {
        int row = rowBase + r;
        if (row < N) {
            float v = out[(size_t)row * DD + col];
            s += v; q += v * v;
        }
    }
    ss[tid] = s; qq[tid] = q;
    __syncthreads();
    if (h == 0) {
        atomicAdd(&g_colsum[col], ss[tid] + ss[tid + 128]);
        atomicAdd(&g_colsumsq[col], qq[tid] + qq[tid + 128]);
    }
}

// ---------------------------------------------------------------------------
__global__ void bn_prep_kernel(const float* __restrict__ gamma,
                               const float* __restrict__ beta,
                               float invN) {
    int j = threadIdx.x;
    if (j < DD) {
        float mu = g_colsum[j] * invN;
        float var = fmaxf(g_colsumsq[j] * invN - mu * mu, 0.f);
        float rs = rsqrtf(var + BN_EPS);
        float sc = gamma[j] * rs;
        g_scale[j] = sc;
        g_shift[j] = beta[j] - mu * sc;
    }
}

__global__ void bn_apply_kernel(float* __restrict__ out, int n4) {
    int i = blockIdx.x * blockDim.x + threadIdx.x;
    if (i >= n4) return;
    int j = (i & 31) * 4;
    float4 v = reinterpret_cast<float4*>(out)[i];
    v.x = v.x * g_scale[j + 0] + g_shift[j + 0];
    v.y = v.y * g_scale[j + 1] + g_shift[j + 1];
    v.z = v.z * g_scale[j + 2] + g_shift[j + 2];
    v.w = v.w * g_scale[j + 3] + g_shift[j + 3];
    reinterpret_cast<float4*>(out)[i] = v;
}

// ---------------------------------------------------------------------------
extern "C" void kernel_launch(void* const* d_in, const int* in_sizes, int n_in,
                              void* d_out, int out_size) {
    const float* x     = (const float*)d_in[0];
    const void*  ei    = d_in[1];
    const float* W_l   = (const float*)d_in[2];
    const float* b_l   = (const float*)d_in[3];
    const float* W_r   = (const float*)d_in[4];
    const float* gamma = (const float*)d_in[5];
    const float* beta  = (const float*)d_in[6];
    float* out         = (float*)d_out;

    const int N = in_sizes[0] / DD;    // 100000
    const int E = in_sizes[1] / 2;     // 1600000
    const int nScanBlocks = (N + 1023) / 1024;
    const int n8x = N * DD / 8;
    const int nodeWarps = (N + 1) / 2;   // one half-warp per node
    const int e4 = (E + 3) / 4;

    init_kernel<<<(N + 255) / 256, 256>>>((const int*)ei, N);
    convert_kernel<<<(n8x + 4096 + 255) / 256, 256>>>(x, W_l, W_r, n8x);
    hist_kernel<<<(e4 + 255) / 256, 256>>>(ei, E);
    scan_p1_kernel<<<nScanBlocks, 256>>>(N);
    scan_p2_kernel<<<1, 128>>>(nScanBlocks);
    scan_p3_kernel<<<(N + 255) / 256, 256>>>(N, E);
    fill_kernel<<<(e4 + 255) / 256, 256>>>(ei, E);
    gather_kernel<<<(nodeWarps + 7) / 8, 256>>>(N);
    gemm_hmma_kernel<<<(N + 127) / 128, 256>>>(b_l, out, N);
    bn_stats_kernel<<<(N + 127) / 128, 256>>>(out, N);
    bn_prep_kernel<<<1, 128>>>(gamma, beta, 1.0f / (float)N);
    bn_apply_kernel<<<(N * (DD / 4) + 255) / 256, 256>>>(out, N * (DD / 4));
}

// round 13
// speedup vs baseline: 1.0125x; 1.0125x over previous
#include <cuda_runtime.h>
#include <cuda_fp16.h>
#include <cstdint>

// Problem constants: N=100000 nodes, D=128, E=1600000 edges.
#define MAX_N 100000
#define MAX_E 2000000
#define DD 128
#define BN_EPS 1e-5f

// Scratch (static __device__ — no allocations allowed)
__device__ __align__(16) __half g_xh[MAX_N * DD];    // fp16 mirror of x
__device__ __align__(16) __half g_aggh[MAX_N * DD];  // fp16 mean-aggregated feats
__device__ __align__(16) __half g_wlh[DD * DD];      // fp16 W_l
__device__ __align__(16) __half g_wrh[DD * DD];      // fp16 W_r
__device__ int   g_degi[MAX_N];
__device__ int   g_rowstart[MAX_N + 1];
__device__ int   g_cursor[MAX_N];
__device__ int   g_csr[MAX_E];
__device__ int   g_bsum[256];
__device__ int   g_boff[256];
__device__ __align__(16) float g_colsum[DD];
__device__ __align__(16) float g_colsumsq[DD];
__device__ int g_idx64;

// ---------------------------------------------------------------------------
// 1. zero degree hist + detect edge_index dtype (int64 => high words all 0)
__global__ void init_kernel(const int* __restrict__ ei32, int N) {
    int i = blockIdx.x * blockDim.x + threadIdx.x;
    if (i < N) g_degi[i] = 0;
    if (i == 0) {
        int ok = 1;
#pragma unroll
        for (int k = 0; k < 64; k++) ok &= (ei32[2 * k + 1] == 0);
        g_idx64 = ok;
    }
}

// 1b. fp16 mirrors: x (n8x groups of 8 floats), then W_l (2048), then W_r (2048)
__global__ void convert_kernel(const float* __restrict__ x,
                               const float* __restrict__ W_l,
                               const float* __restrict__ W_r,
                               int n8x) {
    int i = blockIdx.x * blockDim.x + threadIdx.x;
    const float* src;
    __half* dst;
    int idx;
    if (i < n8x) { src = x; dst = g_xh; idx = i; }
    else if (i < n8x + 2048) { src = W_l; dst = g_wlh; idx = i - n8x; }
    else if (i < n8x + 4096) { src = W_r; dst = g_wrh; idx = i - n8x - 2048; }
    else return;
    float4 a = reinterpret_cast<const float4*>(src)[2 * idx];
    float4 b = reinterpret_cast<const float4*>(src)[2 * idx + 1];
    __half2 h0 = __floats2half2_rn(a.x, a.y);
    __half2 h1 = __floats2half2_rn(a.z, a.w);
    __half2 h2 = __floats2half2_rn(b.x, b.y);
    __half2 h3 = __floats2half2_rn(b.z, b.w);
    uint4 o;
    o.x = *reinterpret_cast<uint32_t*>(&h0);
    o.y = *reinterpret_cast<uint32_t*>(&h1);
    o.z = *reinterpret_cast<uint32_t*>(&h2);
    o.w = *reinterpret_cast<uint32_t*>(&h3);
    reinterpret_cast<uint4*>(dst)[idx] = o;
}

// 2. degree histogram over dst [R11 scalar version]
__global__ void hist_kernel(const void* __restrict__ ei_raw, int E) {
    int e = blockIdx.x * blockDim.x + threadIdx.x;
    if (e >= E) return;
    int dst;
    if (g_idx64) dst = (int)((const long long*)ei_raw)[E + e];
    else         dst = ((const int*)ei_raw)[E + e];
    atomicAdd(&g_degi[dst], 1);
}

// 3. scan pass 1
__global__ void scan_p1_kernel(int N) {
    __shared__ int wsum[8];
    const int t = threadIdx.x;
    const int lane = t & 31, w = t >> 5;
    const int base = blockIdx.x * 1024 + t * 4;

    int v0 = 0, v1 = 0, v2 = 0, v3 = 0;
    if (base + 0 < N) v0 = g_degi[base + 0];
    if (base + 1 < N) v1 = g_degi[base + 1];
    if (base + 2 < N) v2 = g_degi[base + 2];
    if (base + 3 < N) v3 = g_degi[base + 3];
    const int s = v0 + v1 + v2 + v3;

    int incl = s;
#pragma unroll
    for (int o = 1; o < 32; o <<= 1) {
        int n = __shfl_up_sync(0xFFFFFFFFu, incl, o);
        if (lane >= o) incl += n;
    }
    if (lane == 31) wsum[w] = incl;
    __syncthreads();
    if (w == 0) {
        int ws = (lane < 8) ? wsum[lane] : 0;
#pragma unroll
        for (int o = 1; o < 8; o <<= 1) {
            int n = __shfl_up_sync(0xFFFFFFFFu, ws, o);
            if (lane >= o) ws += n;
        }
        if (lane < 8) wsum[lane] = ws;
    }
    __syncthreads();
    const int woff = (w > 0) ? wsum[w - 1] : 0;
    const int te = woff + incl - s;
    if (base + 0 < N) g_rowstart[base + 0] = te;
    if (base + 1 < N) g_rowstart[base + 1] = te + v0;
    if (base + 2 < N) g_rowstart[base + 2] = te + v0 + v1;
    if (base + 3 < N) g_rowstart[base + 3] = te + v0 + v1 + v2;
    if (t == 255) g_bsum[blockIdx.x] = woff + incl;
}

// 4. scan pass 2 (block totals) + zero BN stats
__global__ void scan_p2_kernel(int nb) {
    __shared__ int ws2[4];
    const int t = threadIdx.x;        // 128 threads
    const int lane = t & 31, w = t >> 5;
    int v = (t < nb) ? g_bsum[t] : 0;
    int incl = v;
#pragma unroll
    for (int o = 1; o < 32; o <<= 1) {
        int n = __shfl_up_sync(0xFFFFFFFFu, incl, o);
        if (lane >= o) incl += n;
    }
    if (lane == 31) ws2[w] = incl;
    __syncthreads();
    if (w == 0 && lane < 4) {
        int x = ws2[lane];
#pragma unroll
        for (int o = 1; o < 4; o <<= 1) {
            int n = __shfl_up_sync(0x0000000Fu, x, o);
            if (lane >= o) x += n;
        }
        ws2[lane] = x;
    }
    __syncthreads();
    incl += (w > 0) ? ws2[w - 1] : 0;
    g_boff[t] = incl - v;
    g_colsum[t] = 0.f;
    g_colsumsq[t] = 0.f;
}

// 5. scan pass 3
__global__ void scan_p3_kernel(int N, int E) {
    int i = blockIdx.x * blockDim.x + threadIdx.x;
    if (i < N) {
        int r = g_rowstart[i] + g_boff[i >> 10];
        g_rowstart[i] = r;
        g_cursor[i] = r;
    }
    if (i == 0) g_rowstart[N] = E;
}

// 6. CSR fill [R11 scalar version]
__global__ void fill_kernel(const void* __restrict__ ei_raw, int E) {
    int e = blockIdx.x * blockDim.x + threadIdx.x;
    if (e >= E) return;
    int src, dst;
    if (g_idx64) {
        const long long* p = (const long long*)ei_raw;
        src = (int)p[e]; dst = (int)p[E + e];
    } else {
        const int* p = (const int*)ei_raw;
        src = p[e]; dst = p[E + e];
    }
    int pos = atomicAdd(&g_cursor[dst], 1);
    g_csr[pos] = src;
}

// ---------------------------------------------------------------------------
// 7. Gather-aggregate over fp16 mirror; one HALF-WARP per node. [R9 version]
__device__ __forceinline__ void accum8(float* acc, uint4 v) {
    float2 f;
    f = __half22float2(*reinterpret_cast<__half2*>(&v.x)); acc[0] += f.x; acc[1] += f.y;
    f = __half22float2(*reinterpret_cast<__half2*>(&v.y)); acc[2] += f.x; acc[3] += f.y;
    f = __half22float2(*reinterpret_cast<__half2*>(&v.z)); acc[4] += f.x; acc[5] += f.y;
    f = __half22float2(*reinterpret_cast<__half2*>(&v.w)); acc[6] += f.x; acc[7] += f.y;
}

__global__ __launch_bounds__(256)
void gather_kernel(int N) {
    const int warp = (blockIdx.x * blockDim.x + threadIdx.x) >> 5;
    const int lane = threadIdx.x & 31;
    const int half_id = lane >> 4;
    const int sub = lane & 15;
    const int node = warp * 2 + half_id;
    const unsigned hmask = half_id ? 0xFFFF0000u : 0x0000FFFFu;
    const int hbase = half_id << 4;

    int start = 0, end = 0;
    if (node < N) {
        start = g_rowstart[node];
        end   = g_rowstart[node + 1];
    }

    float acc[8];
#pragma unroll
    for (int k = 0; k < 8; k++) acc[k] = 0.f;

    const uint4* xh = reinterpret_cast<const uint4*>(g_xh);  // 16 uint4 per row

    for (int eb = start; eb < end; eb += 16) {
        int n = end - eb; if (n > 16) n = 16;
        int myid = (sub < n) ? g_csr[eb + sub] : 0;
        int j = 0;
        for (; j + 2 <= n; j += 2) {
            int s0 = __shfl_sync(hmask, myid, hbase + j);
            int s1 = __shfl_sync(hmask, myid, hbase + j + 1);
            uint4 v0 = xh[(size_t)s0 * 16 + sub];
            uint4 v1 = xh[(size_t)s1 * 16 + sub];
            accum8(acc, v0);
            accum8(acc, v1);
        }
        if (j < n) {
            int s0 = __shfl_sync(hmask, myid, hbase + j);
            uint4 v0 = xh[(size_t)s0 * 16 + sub];
            accum8(acc, v0);
        }
    }

    if (node < N) {
        const float inv = 1.0f / fmaxf((float)(end - start), 1.0f);
        __half2 h0 = __floats2half2_rn(acc[0] * inv, acc[1] * inv);
        __half2 h1 = __floats2half2_rn(acc[2] * inv, acc[3] * inv);
        __half2 h2 = __floats2half2_rn(acc[4] * inv, acc[5] * inv);
        __half2 h3 = __floats2half2_rn(acc[6] * inv, acc[7] * inv);
        uint4 o;
        o.x = *reinterpret_cast<uint32_t*>(&h0);
        o.y = *reinterpret_cast<uint32_t*>(&h1);
        o.z = *reinterpret_cast<uint32_t*>(&h2);
        o.w = *reinterpret_cast<uint32_t*>(&h3);
        reinterpret_cast<uint4*>(g_aggh + (size_t)node * DD)[sub] = o;
    }
}

// ---------------------------------------------------------------------------
// cp.async helper: 16B copy with zero-fill when pred is false (src-size=0)
__device__ __forceinline__ void cp16(uint32_t dst_smem, const void* src, bool pred) {
    int sz = pred ? 16 : 0;
    asm volatile("cp.async.cg.shared.global [%0], [%1], 16, %2;"
                 :: "r"(dst_smem), "l"(src), "r"(sz));
}

// ---------------------------------------------------------------------------
// 8. HMMA GEMM with cp.async 2-stage pipeline. [R11 version]
__global__ __launch_bounds__(256, 2)
void gemm_hmma_kernel(const float* __restrict__ b_l,
                      float* __restrict__ out,
                      int N) {
    __shared__ __align__(16) __half sA[2][128 * 40];
    __shared__ __align__(16) __half sB[2][128 * 40];

    const int tid = threadIdx.x;
    const int lane = tid & 31;
    const int wid = tid >> 5;
    const int warp_m = wid & 3;
    const int warp_n = wid >> 2;
    const int rowBase = blockIdx.x * 128;

    float d[2][8][4];
#pragma unroll
    for (int mt = 0; mt < 2; mt++)
#pragma unroll
        for (int nt = 0; nt < 8; nt++)
#pragma unroll
            for (int r = 0; r < 4; r++) d[mt][nt][r] = 0.f;

    const int lr = tid >> 1;          // 0..127: row in tile
    const int lc = (tid & 1) * 16;    // 0 or 16: half-offset within 32
    const int row = rowBase + lr;
    const bool rvalid = row < N;
    const int rclamp = rvalid ? row : 0;

    auto issue_tile = [&](int kt, int st) {
        const __half* srcA = (kt < 4) ? g_aggh : g_xh;
        const __half* srcB = (kt < 4) ? g_wlh : g_wrh;
        const __half* pa = srcA + (size_t)rclamp * DD + (kt & 3) * 32 + lc;
        const __half* pb = srcB + (size_t)lr * DD + (kt & 3) * 32 + lc;
        uint32_t da = (uint32_t)__cvta_generic_to_shared(&sA[st][lr * 40 + lc]);
        uint32_t db = (uint32_t)__cvta_generic_to_shared(&sB[st][lr * 40 + lc]);
        cp16(da, pa, rvalid);
        cp16(da + 16, pa + 8, rvalid);
        cp16(db, pb, true);
        cp16(db + 16, pb + 8, true);
        asm volatile("cp.async.commit_group;");
    };

    issue_tile(0, 0);

    for (int kt = 0; kt < 8; kt++) {
        const int cur = kt & 1;
        if (kt < 7) {
            issue_tile(kt + 1, cur ^ 1);
            asm volatile("cp.async.wait_group 1;");
        } else {
            asm volatile("cp.async.wait_group 0;");
        }
        __syncthreads();

#pragma unroll
        for (int ks = 0; ks < 32; ks += 16) {
            uint32_t a[2][4];
#pragma unroll
            for (int mt = 0; mt < 2; mt++) {
                int arow = warp_m * 32 + mt * 16 + (lane & 15);
                int akk = ks + ((lane >> 4) << 3);
                uint32_t addr = (uint32_t)__cvta_generic_to_shared(&sA[cur][arow * 40 + akk]);
                asm volatile(
                    "ldmatrix.sync.aligned.m8n8.x4.shared.b16 {%0,%1,%2,%3}, [%4];"
                    : "=r"(a[mt][0]), "=r"(a[mt][1]), "=r"(a[mt][2]), "=r"(a[mt][3])
                    : "r"(addr));
            }
            uint32_t b[8][2];
#pragma unroll
            for (int nt = 0; nt < 8; nt++) {
                int brow = warp_n * 64 + nt * 8 + (lane & 7);
                int bkk = ks + ((lane & 8) ? 8 : 0);
                uint32_t addr = (uint32_t)__cvta_generic_to_shared(&sB[cur][brow * 40 + bkk]);
                asm volatile(
                    "ldmatrix.sync.aligned.m8n8.x2.shared.b16 {%0,%1}, [%2];"
                    : "=r"(b[nt][0]), "=r"(b[nt][1])
                    : "r"(addr));
            }
#pragma unroll
            for (int mt = 0; mt < 2; mt++)
#pragma unroll
                for (int nt = 0; nt < 8; nt++) {
                    asm volatile(
                        "mma.sync.aligned.m16n8k16.row.col.f32.f16.f16.f32 "
                        "{%0,%1,%2,%3}, {%4,%5,%6,%7}, {%8,%9}, {%0,%1,%2,%3};"
                        : "+f"(d[mt][nt][0]), "+f"(d[mt][nt][1]),
                          "+f"(d[mt][nt][2]), "+f"(d[mt][nt][3])
                        : "r"(a[mt][0]), "r"(a[mt][1]), "r"(a[mt][2]), "r"(a[mt][3]),
                          "r"(b[nt][0]), "r"(b[nt][1]));
                }
        }
        __syncthreads();
    }

    // --- epilogue: +bias, relu, store fp32 h ---
#pragma unroll
    for (int nt = 0; nt < 8; nt++) {
        int col = warp_n * 64 + nt * 8 + ((lane & 3) << 1);
        float b0 = __ldg(&b_l[col]);
        float b1 = __ldg(&b_l[col + 1]);
#pragma unroll
        for (int mt = 0; mt < 2; mt++) {
            int orow = rowBase + warp_m * 32 + mt * 16 + (lane >> 2);
            if (orow < N) {
                float2 v = make_float2(fmaxf(d[mt][nt][0] + b0, 0.f),
                                       fmaxf(d[mt][nt][1] + b1, 0.f));
                *reinterpret_cast<float2*>(out + (size_t)orow * DD + col) = v;
            }
            if (orow + 8 < N) {
                float2 v = make_float2(fmaxf(d[mt][nt][2] + b0, 0.f),
                                       fmaxf(d[mt][nt][3] + b1, 0.f));
                *reinterpret_cast<float2*>(out + (size_t)(orow + 8) * DD + col) = v;
            }
        }
    }
}

// ---------------------------------------------------------------------------
// 9. BN column stats over out (h). One block per 128 rows. [R9 version]
__global__ __launch_bounds__(256)
void bn_stats_kernel(const float* __restrict__ out, int N) {
    __shared__ float ss[256], qq[256];
    const int tid = threadIdx.x;
    const int col = tid & 127;
    const int h = tid >> 7;
    const int rowBase = blockIdx.x * 128;

    float s = 0.f, q = 0.f;
    for (int r = h; r < 128; r += 2) {
        int row = rowBase + r;
        if (row < N) {
            float v = out[(size_t)row * DD + col];
            s += v; q += v * v;
        }
    }
    ss[tid] = s; qq[tid] = q;
    __syncthreads();
    if (h == 0) {
        atomicAdd(&g_colsum[col], ss[tid] + ss[tid + 128]);
        atomicAdd(&g_colsumsq[col], qq[tid] + qq[tid + 128]);
    }
}

// ---------------------------------------------------------------------------
// 10. BN apply with fused scale/shift computation (bn_prep folded in).
// Each block computes scale/shift from colsum/colsumsq into smem, then applies.
__global__ __launch_bounds__(256)
void bn_apply_kernel(float* __restrict__ out, int n4, float invN,
                     const float* __restrict__ gamma,
                     const float* __restrict__ beta) {
    __shared__ float sscale[DD], sshift[DD];
    const int tid = threadIdx.x;
    if (tid < DD) {
        float mu = g_colsum[tid] * invN;
        float var = fmaxf(g_colsumsq[tid] * invN - mu * mu, 0.f);
        float rs = rsqrtf(var + BN_EPS);
        float sc = gamma[tid] * rs;
        sscale[tid] = sc;
        sshift[tid] = beta[tid] - mu * sc;
    }
    __syncthreads();

    int i = blockIdx.x * blockDim.x + tid;
    if (i >= n4) return;
    int j = (i & 31) * 4;
    float4 v = reinterpret_cast<float4*>(out)[i];
    v.x = v.x * sscale[j + 0] + sshift[j + 0];
    v.y = v.y * sscale[j + 1] + sshift[j + 1];
    v.z = v.z * sscale[j + 2] + sshift[j + 2];
    v.w = v.w * sscale[j + 3] + sshift[j + 3];
    reinterpret_cast<float4*>(out)[i] = v;
}

// ---------------------------------------------------------------------------
extern "C" void kernel_launch(void* const* d_in, const int* in_sizes, int n_in,
                              void* d_out, int out_size) {
    const float* x     = (const float*)d_in[0];
    const void*  ei    = d_in[1];
    const float* W_l   = (const float*)d_in[2];
    const float* b_l   = (const float*)d_in[3];
    const float* W_r   = (const float*)d_in[4];
    const float* gamma = (const float*)d_in[5];
    const float* beta  = (const float*)d_in[6];
    float* out         = (float*)d_out;

    const int N = in_sizes[0] / DD;    // 100000
    const int E = in_sizes[1] / 2;     // 1600000
    const int nScanBlocks = (N + 1023) / 1024;
    const int n8x = N * DD / 8;
    const int nodeWarps = (N + 1) / 2;   // one half-warp per node

    init_kernel<<<(N + 255) / 256, 256>>>((const int*)ei, N);
    convert_kernel<<<(n8x + 4096 + 255) / 256, 256>>>(x, W_l, W_r, n8x);
    hist_kernel<<<(E + 255) / 256, 256>>>(ei, E);
    scan_p1_kernel<<<nScanBlocks, 256>>>(N);
    scan_p2_kernel<<<1, 128>>>(nScanBlocks);
    scan_p3_kernel<<<(N + 255) / 256, 256>>>(N, E);
    fill_kernel<<<(E + 255) / 256, 256>>>(ei, E);
    gather_kernel<<<(nodeWarps + 7) / 8, 256>>>(N);
    gemm_hmma_kernel<<<(N + 127) / 128, 256>>>(b_l, out, N);
    bn_stats_kernel<<<(N + 127) / 128, 256>>>(out, N);
    bn_apply_kernel<<<(N * (DD / 4) + 255) / 256, 256>>>(out, N * (DD / 4),
                                                         1.0f / (float)N, gamma, beta);
}

// round 14
// speedup vs baseline: 1.0371x; 1.0242x over previous
#include <cuda_runtime.h>
#include <cuda_fp16.h>
#include <cstdint>

// Problem constants: N=100000 nodes, D=128, E=1600000 edges.
#define MAX_N 100000
#define MAX_E 2000000
#define DD 128
#define BN_EPS 1e-5f

// Scratch (static __device__ — no allocations allowed)
__device__ __align__(16) __half g_xh[MAX_N * DD];    // fp16 mirror of x
__device__ __align__(16) __half g_aggh[MAX_N * DD];  // fp16 mean-aggregated feats
__device__ __align__(16) __half g_wlh[DD * DD];      // fp16 W_l
__device__ __align__(16) __half g_wrh[DD * DD];      // fp16 W_r
__device__ int   g_degi[MAX_N];
__device__ int   g_rowstart[MAX_N + 1];
__device__ int   g_cursor[MAX_N];
__device__ int   g_csr[MAX_E];
__device__ int   g_bsum[256];
__device__ int   g_boff[256];
__device__ __align__(16) float g_colsum[DD];
__device__ __align__(16) float g_colsumsq[DD];
__device__ int g_idx64;

// ---------------------------------------------------------------------------
// 1. zero degree hist + detect edge_index dtype (int64 => high words all 0)
__global__ void init_kernel(const int* __restrict__ ei32, int N) {
    int i = blockIdx.x * blockDim.x + threadIdx.x;
    if (i < N) g_degi[i] = 0;
    if (i == 0) {
        int ok = 1;
#pragma unroll
        for (int k = 0; k < 64; k++) ok &= (ei32[2 * k + 1] == 0);
        g_idx64 = ok;
    }
}

// 1b. fp16 mirrors: x (n8x groups of 8 floats), then W_l (2048), then W_r (2048)
__global__ void convert_kernel(const float* __restrict__ x,
                               const float* __restrict__ W_l,
                               const float* __restrict__ W_r,
                               int n8x) {
    int i = blockIdx.x * blockDim.x + threadIdx.x;
    const float* src;
    __half* dst;
    int idx;
    if (i < n8x) { src = x; dst = g_xh; idx = i; }
    else if (i < n8x + 2048) { src = W_l; dst = g_wlh; idx = i - n8x; }
    else if (i < n8x + 4096) { src = W_r; dst = g_wrh; idx = i - n8x - 2048; }
    else return;
    float4 a = reinterpret_cast<const float4*>(src)[2 * idx];
    float4 b = reinterpret_cast<const float4*>(src)[2 * idx + 1];
    __half2 h0 = __floats2half2_rn(a.x, a.y);
    __half2 h1 = __floats2half2_rn(a.z, a.w);
    __half2 h2 = __floats2half2_rn(b.x, b.y);
    __half2 h3 = __floats2half2_rn(b.z, b.w);
    uint4 o;
    o.x = *reinterpret_cast<uint32_t*>(&h0);
    o.y = *reinterpret_cast<uint32_t*>(&h1);
    o.z = *reinterpret_cast<uint32_t*>(&h2);
    o.w = *reinterpret_cast<uint32_t*>(&h3);
    reinterpret_cast<uint4*>(dst)[idx] = o;
}

// 2. degree histogram over dst
__global__ void hist_kernel(const void* __restrict__ ei_raw, int E) {
    int e = blockIdx.x * blockDim.x + threadIdx.x;
    if (e >= E) return;
    int dst;
    if (g_idx64) dst = (int)((const long long*)ei_raw)[E + e];
    else         dst = ((const int*)ei_raw)[E + e];
    atomicAdd(&g_degi[dst], 1);
}

// 3. scan pass 1
__global__ void scan_p1_kernel(int N) {
    __shared__ int wsum[8];
    const int t = threadIdx.x;
    const int lane = t & 31, w = t >> 5;
    const int base = blockIdx.x * 1024 + t * 4;

    int v0 = 0, v1 = 0, v2 = 0, v3 = 0;
    if (base + 0 < N) v0 = g_degi[base + 0];
    if (base + 1 < N) v1 = g_degi[base + 1];
    if (base + 2 < N) v2 = g_degi[base + 2];
    if (base + 3 < N) v3 = g_degi[base + 3];
    const int s = v0 + v1 + v2 + v3;

    int incl = s;
#pragma unroll
    for (int o = 1; o < 32; o <<= 1) {
        int n = __shfl_up_sync(0xFFFFFFFFu, incl, o);
        if (lane >= o) incl += n;
    }
    if (lane == 31) wsum[w] = incl;
    __syncthreads();
    if (w == 0) {
        int ws = (lane < 8) ? wsum[lane] : 0;
#pragma unroll
        for (int o = 1; o < 8; o <<= 1) {
            int n = __shfl_up_sync(0xFFFFFFFFu, ws, o);
            if (lane >= o) ws += n;
        }
        if (lane < 8) wsum[lane] = ws;
    }
    __syncthreads();
    const int woff = (w > 0) ? wsum[w - 1] : 0;
    const int te = woff + incl - s;
    if (base + 0 < N) g_rowstart[base + 0] = te;
    if (base + 1 < N) g_rowstart[base + 1] = te + v0;
    if (base + 2 < N) g_rowstart[base + 2] = te + v0 + v1;
    if (base + 3 < N) g_rowstart[base + 3] = te + v0 + v1 + v2;
    if (t == 255) g_bsum[blockIdx.x] = woff + incl;
}

// 4. scan pass 2 (block totals) + zero BN stats
__global__ void scan_p2_kernel(int nb) {
    __shared__ int ws2[4];
    const int t = threadIdx.x;        // 128 threads
    const int lane = t & 31, w = t >> 5;
    int v = (t < nb) ? g_bsum[t] : 0;
    int incl = v;
#pragma unroll
    for (int o = 1; o < 32; o <<= 1) {
        int n = __shfl_up_sync(0xFFFFFFFFu, incl, o);
        if (lane >= o) incl += n;
    }
    if (lane == 31) ws2[w] = incl;
    __syncthreads();
    if (w == 0 && lane < 4) {
        int x = ws2[lane];
#pragma unroll
        for (int o = 1; o < 4; o <<= 1) {
            int n = __shfl_up_sync(0x0000000Fu, x, o);
            if (lane >= o) x += n;
        }
        ws2[lane] = x;
    }
    __syncthreads();
    incl += (w > 0) ? ws2[w - 1] : 0;
    g_boff[t] = incl - v;
    g_colsum[t] = 0.f;
    g_colsumsq[t] = 0.f;
}

// 5. scan pass 3
__global__ void scan_p3_kernel(int N, int E) {
    int i = blockIdx.x * blockDim.x + threadIdx.x;
    if (i < N) {
        int r = g_rowstart[i] + g_boff[i >> 10];
        g_rowstart[i] = r;
        g_cursor[i] = r;
    }
    if (i == 0) g_rowstart[N] = E;
}

// 6. CSR fill
__global__ void fill_kernel(const void* __restrict__ ei_raw, int E) {
    int e = blockIdx.x * blockDim.x + threadIdx.x;
    if (e >= E) return;
    int src, dst;
    if (g_idx64) {
        const long long* p = (const long long*)ei_raw;
        src = (int)p[e]; dst = (int)p[E + e];
    } else {
        const int* p = (const int*)ei_raw;
        src = p[e]; dst = p[E + e];
    }
    int pos = atomicAdd(&g_cursor[dst], 1);
    g_csr[pos] = src;
}

// ---------------------------------------------------------------------------
// 7. Gather-aggregate over fp16 mirror; one HALF-WARP per node; unroll-4
// main loop (4 independent LDG.128 in flight per half-warp).
__device__ __forceinline__ void accum8(float* acc, uint4 v) {
    float2 f;
    f = __half22float2(*reinterpret_cast<__half2*>(&v.x)); acc[0] += f.x; acc[1] += f.y;
    f = __half22float2(*reinterpret_cast<__half2*>(&v.y)); acc[2] += f.x; acc[3] += f.y;
    f = __half22float2(*reinterpret_cast<__half2*>(&v.z)); acc[4] += f.x; acc[5] += f.y;
    f = __half22float2(*reinterpret_cast<__half2*>(&v.w)); acc[6] += f.x; acc[7] += f.y;
}

__global__ __launch_bounds__(256)
void gather_kernel(int N) {
    const int warp = (blockIdx.x * blockDim.x + threadIdx.x) >> 5;
    const int lane = threadIdx.x & 31;
    const int half_id = lane >> 4;
    const int sub = lane & 15;
    const int node = warp * 2 + half_id;
    const unsigned hmask = half_id ? 0xFFFF0000u : 0x0000FFFFu;
    const int hbase = half_id << 4;

    int start = 0, end = 0;
    if (node < N) {
        start = g_rowstart[node];
        end   = g_rowstart[node + 1];
    }

    float acc[8];
#pragma unroll
    for (int k = 0; k < 8; k++) acc[k] = 0.f;

    const uint4* xh = reinterpret_cast<const uint4*>(g_xh);  // 16 uint4 per row

    for (int eb = start; eb < end; eb += 16) {
        int n = end - eb; if (n > 16) n = 16;
        int myid = (sub < n) ? g_csr[eb + sub] : 0;
        int j = 0;
        // 4 neighbor rows in flight per half-warp
        for (; j + 4 <= n; j += 4) {
            int s0 = __shfl_sync(hmask, myid, hbase + j);
            int s1 = __shfl_sync(hmask, myid, hbase + j + 1);
            int s2 = __shfl_sync(hmask, myid, hbase + j + 2);
            int s3 = __shfl_sync(hmask, myid, hbase + j + 3);
            uint4 v0 = xh[(size_t)s0 * 16 + sub];
            uint4 v1 = xh[(size_t)s1 * 16 + sub];
            uint4 v2 = xh[(size_t)s2 * 16 + sub];
            uint4 v3 = xh[(size_t)s3 * 16 + sub];
            accum8(acc, v0);
            accum8(acc, v1);
            accum8(acc, v2);
            accum8(acc, v3);
        }
        for (; j + 2 <= n; j += 2) {
            int s0 = __shfl_sync(hmask, myid, hbase + j);
            int s1 = __shfl_sync(hmask, myid, hbase + j + 1);
            uint4 v0 = xh[(size_t)s0 * 16 + sub];
            uint4 v1 = xh[(size_t)s1 * 16 + sub];
            accum8(acc, v0);
            accum8(acc, v1);
        }
        if (j < n) {
            int s0 = __shfl_sync(hmask, myid, hbase + j);
            uint4 v0 = xh[(size_t)s0 * 16 + sub];
            accum8(acc, v0);
        }
    }

    if (node < N) {
        const float inv = 1.0f / fmaxf((float)(end - start), 1.0f);
        __half2 h0 = __floats2half2_rn(acc[0] * inv, acc[1] * inv);
        __half2 h1 = __floats2half2_rn(acc[2] * inv, acc[3] * inv);
        __half2 h2 = __floats2half2_rn(acc[4] * inv, acc[5] * inv);
        __half2 h3 = __floats2half2_rn(acc[6] * inv, acc[7] * inv);
        uint4 o;
        o.x = *reinterpret_cast<uint32_t*>(&h0);
        o.y = *reinterpret_cast<uint32_t*>(&h1);
        o.z = *reinterpret_cast<uint32_t*>(&h2);
        o.w = *reinterpret_cast<uint32_t*>(&h3);
        reinterpret_cast<uint4*>(g_aggh + (size_t)node * DD)[sub] = o;
    }
}

// ---------------------------------------------------------------------------
// cp.async helper: 16B copy with zero-fill when pred is false (src-size=0)
__device__ __forceinline__ void cp16(uint32_t dst_smem, const void* src, bool pred) {
    int sz = pred ? 16 : 0;
    asm volatile("cp.async.cg.shared.global [%0], [%1], 16, %2;"
                 :: "r"(dst_smem), "l"(src), "r"(sz));
}

// ---------------------------------------------------------------------------
// 8. HMMA GEMM with cp.async 2-stage pipeline. [R11 version]
__global__ __launch_bounds__(256, 2)
void gemm_hmma_kernel(const float* __restrict__ b_l,
                      float* __restrict__ out,
                      int N) {
    __shared__ __align__(16) __half sA[2][128 * 40];
    __shared__ __align__(16) __half sB[2][128 * 40];

    const int tid = threadIdx.x;
    const int lane = tid & 31;
    const int wid = tid >> 5;
    const int warp_m = wid & 3;
    const int warp_n = wid >> 2;
    const int rowBase = blockIdx.x * 128;

    float d[2][8][4];
#pragma unroll
    for (int mt = 0; mt < 2; mt++)
#pragma unroll
        for (int nt = 0; nt < 8; nt++)
#pragma unroll
            for (int r = 0; r < 4; r++) d[mt][nt][r] = 0.f;

    const int lr = tid >> 1;          // 0..127: row in tile
    const int lc = (tid & 1) * 16;    // 0 or 16: half-offset within 32
    const int row = rowBase + lr;
    const bool rvalid = row < N;
    const int rclamp = rvalid ? row : 0;

    auto issue_tile = [&](int kt, int st) {
        const __half* srcA = (kt < 4) ? g_aggh : g_xh;
        const __half* srcB = (kt < 4) ? g_wlh : g_wrh;
        const __half* pa = srcA + (size_t)rclamp * DD + (kt & 3) * 32 + lc;
        const __half* pb = srcB + (size_t)lr * DD + (kt & 3) * 32 + lc;
        uint32_t da = (uint32_t)__cvta_generic_to_shared(&sA[st][lr * 40 + lc]);
        uint32_t db = (uint32_t)__cvta_generic_to_shared(&sB[st][lr * 40 + lc]);
        cp16(da, pa, rvalid);
        cp16(da + 16, pa + 8, rvalid);
        cp16(db, pb, true);
        cp16(db + 16, pb + 8, true);
        asm volatile("cp.async.commit_group;");
    };

    issue_tile(0, 0);

    for (int kt = 0; kt < 8; kt++) {
        const int cur = kt & 1;
        if (kt < 7) {
            issue_tile(kt + 1, cur ^ 1);
            asm volatile("cp.async.wait_group 1;");
        } else {
            asm volatile("cp.async.wait_group 0;");
        }
        __syncthreads();

#pragma unroll
        for (int ks = 0; ks < 32; ks += 16) {
            uint32_t a[2][4];
#pragma unroll
            for (int mt = 0; mt < 2; mt++) {
                int arow = warp_m * 32 + mt * 16 + (lane & 15);
                int akk = ks + ((lane >> 4) << 3);
                uint32_t addr = (uint32_t)__cvta_generic_to_shared(&sA[cur][arow * 40 + akk]);
                asm volatile(
                    "ldmatrix.sync.aligned.m8n8.x4.shared.b16 {%0,%1,%2,%3}, [%4];"
                    : "=r"(a[mt][0]), "=r"(a[mt][1]), "=r"(a[mt][2]), "=r"(a[mt][3])
                    : "r"(addr));
            }
            uint32_t b[8][2];
#pragma unroll
            for (int nt = 0; nt < 8; nt++) {
                int brow = warp_n * 64 + nt * 8 + (lane & 7);
                int bkk = ks + ((lane & 8) ? 8 : 0);
                uint32_t addr = (uint32_t)__cvta_generic_to_shared(&sB[cur][brow * 40 + bkk]);
                asm volatile(
                    "ldmatrix.sync.aligned.m8n8.x2.shared.b16 {%0,%1}, [%2];"
                    : "=r"(b[nt][0]), "=r"(b[nt][1])
                    : "r"(addr));
            }
#pragma unroll
            for (int mt = 0; mt < 2; mt++)
#pragma unroll
                for (int nt = 0; nt < 8; nt++) {
                    asm volatile(
                        "mma.sync.aligned.m16n8k16.row.col.f32.f16.f16.f32 "
                        "{%0,%1,%2,%3}, {%4,%5,%6,%7}, {%8,%9}, {%0,%1,%2,%3};"
                        : "+f"(d[mt][nt][0]), "+f"(d[mt][nt][1]),
                          "+f"(d[mt][nt][2]), "+f"(d[mt][nt][3])
                        : "r"(a[mt][0]), "r"(a[mt][1]), "r"(a[mt][2]), "r"(a[mt][3]),
                          "r"(b[nt][0]), "r"(b[nt][1]));
                }
        }
        __syncthreads();
    }

    // --- epilogue: +bias, relu, store fp32 h ---
#pragma unroll
    for (int nt = 0; nt < 8; nt++) {
        int col = warp_n * 64 + nt * 8 + ((lane & 3) << 1);
        float b0 = __ldg(&b_l[col]);
        float b1 = __ldg(&b_l[col + 1]);
#pragma unroll
        for (int mt = 0; mt < 2; mt++) {
            int orow = rowBase + warp_m * 32 + mt * 16 + (lane >> 2);
            if (orow < N) {
                float2 v = make_float2(fmaxf(d[mt][nt][0] + b0, 0.f),
                                       fmaxf(d[mt][nt][1] + b1, 0.f));
                *reinterpret_cast<float2*>(out + (size_t)orow * DD + col) = v;
            }
            if (orow + 8 < N) {
                float2 v = make_float2(fmaxf(d[mt][nt][2] + b0, 0.f),
                                       fmaxf(d[mt][nt][3] + b1, 0.f));
                *reinterpret_cast<float2*>(out + (size_t)(orow + 8) * DD + col) = v;
            }
        }
    }
}

// ---------------------------------------------------------------------------
// 9. BN column stats over out (h). One block per 128 rows. [R9 version]
__global__ __launch_bounds__(256)
void bn_stats_kernel(const float* __restrict__ out, int N) {
    __shared__ float ss[256], qq[256];
    const int tid = threadIdx.x;
    const int col = tid & 127;
    const int h = tid >> 7;
    const int rowBase = blockIdx.x * 128;

    float s = 0.f, q = 0.f;
    for (int r = h; r < 128; r += 2) {
        int row = rowBase + r;
        if (row < N) {
            float v = out[(size_t)row * DD + col];
            s += v; q += v * v;
        }
    }
    ss[tid] = s; qq[tid] = q;
    __syncthreads();
    if (h == 0) {
        atomicAdd(&g_colsum[col], ss[tid] + ss[tid + 128]);
        atomicAdd(&g_colsumsq[col], qq[tid] + qq[tid + 128]);
    }
}

// ---------------------------------------------------------------------------
// 10. BN apply with fused scale/shift computation (bn_prep folded in).
__global__ __launch_bounds__(256)
void bn_apply_kernel(float* __restrict__ out, int n4, float invN,
                     const float* __restrict__ gamma,
                     const float* __restrict__ beta) {
    __shared__ float sscale[DD], sshift[DD];
    const int tid = threadIdx.x;
    if (tid < DD) {
        float mu = g_colsum[tid] * invN;
        float var = fmaxf(g_colsumsq[tid] * invN - mu * mu, 0.f);
        float rs = rsqrtf(var + BN_EPS);
        float sc = gamma[tid] * rs;
        sscale[tid] = sc;
        sshift[tid] = beta[tid] - mu * sc;
    }
    __syncthreads();

    int i = blockIdx.x * blockDim.x + tid;
    if (i >= n4) return;
    int j = (i & 31) * 4;
    float4 v = reinterpret_cast<float4*>(out)[i];
    v.x = v.x * sscale[j + 0] + sshift[j + 0];
    v.y = v.y * sscale[j + 1] + sshift[j + 1];
    v.z = v.z * sscale[j + 2] + sshift[j + 2];
    v.w = v.w * sscale[j + 3] + sshift[j + 3];
    reinterpret_cast<float4*>(out)[i] = v;
}

// ---------------------------------------------------------------------------
extern "C" void kernel_launch(void* const* d_in, const int* in_sizes, int n_in,
                              void* d_out, int out_size) {
    const float* x     = (const float*)d_in[0];
    const void*  ei    = d_in[1];
    const float* W_l   = (const float*)d_in[2];
    const float* b_l   = (const float*)d_in[3];
    const float* W_r   = (const float*)d_in[4];
    const float* gamma = (const float*)d_in[5];
    const float* beta  = (const float*)d_in[6];
    float* out         = (float*)d_out;

    const int N = in_sizes[0] / DD;    // 100000
    const int E = in_sizes[1] / 2;     // 1600000
    const int nScanBlocks = (N + 1023) / 1024;
    const int n8x = N * DD / 8;
    const int nodeWarps = (N + 1) / 2;   // one half-warp per node

    init_kernel<<<(N + 255) / 256, 256>>>((const int*)ei, N);
    convert_kernel<<<(n8x + 4096 + 255) / 256, 256>>>(x, W_l, W_r, n8x);
    hist_kernel<<<(E + 255) / 256, 256>>>(ei, E);
    scan_p1_kernel<<<nScanBlocks, 256>>>(N);
    scan_p2_kernel<<<1, 128>>>(nScanBlocks);
    scan_p3_kernel<<<(N + 255) / 256, 256>>>(N, E);
    fill_kernel<<<(E + 255) / 256, 256>>>(ei, E);
    gather_kernel<<<(nodeWarps + 7) / 8, 256>>>(N);
    gemm_hmma_kernel<<<(N + 127) / 128, 256>>>(b_l, out, N);
    bn_stats_kernel<<<(N + 127) / 128, 256>>>(out, N);
    bn_apply_kernel<<<(N * (DD / 4) + 255) / 256, 256>>>(out, N * (DD / 4),
                                                         1.0f / (float)N, gamma, beta);
}